// round 4
// baseline (speedup 1.0000x reference)
#include <cuda_runtime.h>

#define BATCH 2
#define CHAN  128
#define NTOK  784
#define INV_T (1.0f / 11.313708498984761f)
#define INV_C (1.0f / 128.0f)
#define LOG2E 1.4426950408889634f

// ---------------------------------------------------------------------------
// Kernel 1: L1-distance logits.
// logits[b,k,q] = (1/C) * sum_c | q[b,c,q]/T - k[b,c,k] |
// Written directly into the attn region of d_out (softmax runs in-place).
// Block: 64(k) x 64(q) tile, 256 threads, each thread computes 4x4 outputs.
// ---------------------------------------------------------------------------
__global__ void l1_logits_kernel(const float* __restrict__ q,
                                 const float* __restrict__ k,
                                 float* __restrict__ attn)
{
    const int b  = blockIdx.z;
    const int k0 = blockIdx.y * 64;
    const int q0 = blockIdx.x * 64;

    __shared__ float qs[8][64];
    __shared__ float ks[8][64];

    const int tid = threadIdx.x;        // 0..255
    const int tx  = tid & 15;           // q-group (4 q's each)
    const int ty  = tid >> 4;           // k-group (4 k's each)

    const float* qb = q + (size_t)b * CHAN * NTOK;
    const float* kb = k + (size_t)b * CHAN * NTOK;

    float acc[4][4] = {};

    for (int c0 = 0; c0 < CHAN; c0 += 8) {
        // Load 8x64 chunk of q (scaled) and k. 512 floats each; 2 per thread.
        #pragma unroll
        for (int r = 0; r < 2; r++) {
            int i   = tid + r * 256;
            int cc  = i >> 6;
            int col = i & 63;
            int qi = q0 + col; if (qi >= NTOK) qi = NTOK - 1;   // clamp (safe: OOB never written)
            int ki = k0 + col; if (ki >= NTOK) ki = NTOK - 1;
            qs[cc][col] = qb[(size_t)(c0 + cc) * NTOK + qi] * INV_T;
            ks[cc][col] = kb[(size_t)(c0 + cc) * NTOK + ki];
        }
        __syncthreads();

        #pragma unroll
        for (int cc = 0; cc < 8; cc++) {
            float rq[4], rk[4];
            #pragma unroll
            for (int i = 0; i < 4; i++) rq[i] = qs[cc][tx * 4 + i];
            #pragma unroll
            for (int j = 0; j < 4; j++) rk[j] = ks[cc][ty * 4 + j];
            #pragma unroll
            for (int j = 0; j < 4; j++)
                #pragma unroll
                for (int i = 0; i < 4; i++)
                    acc[j][i] += fabsf(rq[i] - rk[j]);
        }
        __syncthreads();
    }

    float* ab = attn + (size_t)b * NTOK * NTOK;
    #pragma unroll
    for (int j = 0; j < 4; j++) {
        int kk = k0 + ty * 4 + j;
        if (kk >= NTOK) continue;
        #pragma unroll
        for (int i = 0; i < 4; i++) {
            int qq = q0 + tx * 4 + i;
            if (qq < NTOK)
                ab[(size_t)kk * NTOK + qq] = acc[j][i] * INV_C;
        }
    }
}

// ---------------------------------------------------------------------------
// Kernel 2: in-place softmax over the last dim (q) of attn[b,k,:].
// One block (256 threads) per row; each thread owns 4 strided elements.
// ---------------------------------------------------------------------------
__global__ void softmax_kernel(float* __restrict__ attn)
{
    const int row = blockIdx.x;               // b*NTOK + k
    float* a = attn + (size_t)row * NTOK;
    const int tid = threadIdx.x;              // 0..255

    float v[4];
    float mx = -1e30f;
    #pragma unroll
    for (int i = 0; i < 4; i++) {
        int idx = tid + i * 256;
        v[i] = (idx < NTOK) ? a[idx] : -1e30f;
        mx = fmaxf(mx, v[i]);
    }

    __shared__ float smax[8];
    __shared__ float ssum[8];

    #pragma unroll
    for (int o = 16; o; o >>= 1)
        mx = fmaxf(mx, __shfl_xor_sync(0xffffffffu, mx, o));
    if ((tid & 31) == 0) smax[tid >> 5] = mx;
    __syncthreads();

    float bm = smax[0];
    #pragma unroll
    for (int w = 1; w < 8; w++) bm = fmaxf(bm, smax[w]);

    float s = 0.0f;
    #pragma unroll
    for (int i = 0; i < 4; i++) {
        v[i] = exp2f((v[i] - bm) * LOG2E);    // OOB lanes: exp(-huge)=0
        s += v[i];
    }

    #pragma unroll
    for (int o = 16; o; o >>= 1)
        s += __shfl_xor_sync(0xffffffffu, s, o);
    if ((tid & 31) == 0) ssum[tid >> 5] = s;
    __syncthreads();

    float bs = 0.0f;
    #pragma unroll
    for (int w = 0; w < 8; w++) bs += ssum[w];
    float inv = __frcp_rn(bs);

    #pragma unroll
    for (int i = 0; i < 4; i++) {
        int idx = tid + i * 256;
        if (idx < NTOK) a[idx] = v[i] * inv;
    }
}

// ---------------------------------------------------------------------------
// Kernel 3: out[b,c,k] = sum_q v[b,c,q] * attn[b,k,q]
// Tiled 32(c) x 32(k), 256 threads, each thread 2x2 outputs, q-chunks of 32.
// ---------------------------------------------------------------------------
__global__ void out_gemm_kernel(const float* __restrict__ v,
                                const float* __restrict__ attn,
                                float* __restrict__ out)
{
    const int b  = blockIdx.z;
    const int c0 = blockIdx.y * 32;
    const int k0 = blockIdx.x * 32;

    __shared__ float vs[32][33];
    __shared__ float as[32][33];

    const int tid = threadIdx.x;        // 0..255
    const int tx  = tid & 15;           // k-pair
    const int ty  = tid >> 4;           // c-pair

    const float* vb = v    + (size_t)b * CHAN * NTOK;
    const float* ab = attn + (size_t)b * NTOK * NTOK;

    float acc[2][2] = {};

    for (int q0 = 0; q0 < NTOK; q0 += 32) {
        #pragma unroll
        for (int r = 0; r < 4; r++) {
            int i   = tid + r * 256;
            int row = i >> 5;
            int col = i & 31;
            int qq = q0 + col;
            // V tile: clamp q (garbage harmless: paired attn entry is 0)
            int qv = (qq < NTOK) ? qq : NTOK - 1;
            vs[row][col] = vb[(size_t)(c0 + row) * NTOK + qv];
            // A tile: zero-fill OOB q, clamp OOB k row (never used for writes)
            int kr = k0 + row; if (kr >= NTOK) kr = NTOK - 1;
            as[row][col] = (qq < NTOK) ? ab[(size_t)kr * NTOK + qq] : 0.0f;
        }
        __syncthreads();

        #pragma unroll
        for (int qq = 0; qq < 32; qq++) {
            float rv0 = vs[ty * 2 + 0][qq];
            float rv1 = vs[ty * 2 + 1][qq];
            float ra0 = as[tx * 2 + 0][qq];
            float ra1 = as[tx * 2 + 1][qq];
            acc[0][0] += rv0 * ra0;
            acc[0][1] += rv0 * ra1;
            acc[1][0] += rv1 * ra0;
            acc[1][1] += rv1 * ra1;
        }
        __syncthreads();
    }

    float* ob = out + (size_t)b * CHAN * NTOK;
    #pragma unroll
    for (int j = 0; j < 2; j++) {
        int cc = c0 + ty * 2 + j;
        #pragma unroll
        for (int i = 0; i < 2; i++) {
            int kk = k0 + tx * 2 + i;
            if (kk < NTOK)
                ob[(size_t)cc * NTOK + kk] = acc[j][i];
        }
    }
}

// ---------------------------------------------------------------------------
extern "C" void kernel_launch(void* const* d_in, const int* in_sizes, int n_in,
                              void* d_out, int out_size)
{
    const float* q = (const float*)d_in[0];
    const float* k = (const float*)d_in[1];
    const float* v = (const float*)d_in[2];

    float* out_ptr  = (float*)d_out;                         // [B, C, N]
    float* attn_ptr = out_ptr + (size_t)BATCH * CHAN * NTOK; // [B, N, N]

    dim3 g1((NTOK + 63) / 64, (NTOK + 63) / 64, BATCH);      // 13 x 13 x 2
    l1_logits_kernel<<<g1, 256>>>(q, k, attn_ptr);

    softmax_kernel<<<BATCH * NTOK, 256>>>(attn_ptr);

    dim3 g3((NTOK + 31) / 32, CHAN / 32, BATCH);             // 25 x 4 x 2
    out_gemm_kernel<<<g3, 256>>>(v, attn_ptr, out_ptr);
}